// round 13
// baseline (speedup 1.0000x reference)
#include <cuda_runtime.h>
#include <cuda_fp16.h>
#include <math.h>
#include <stdint.h>

// ---------------- problem dims ----------------
#define HID     2048
#define HEADS   16
#define SEQ     2048
#define BATCH   2
#define BS      (BATCH*SEQ)          // 4096
#define QLORA   1024
#define QH      192
#define NOPE    128
#define ROPED   64
#define VH      128
#define KVL     512
#define CKV_W   576
#define CQK_W   1600                 // QLORA + CKV_W (merged down-proj output)
#define QW      (HEADS*QH)           // 3072
#define KVW     (HEADS*(NOPE+VH))    // 4096

// ---------------- scratch (all fp16 intermediates) ----------------
__device__ __half g_x16 [(size_t)BS * HID];
__device__ __half g_cqk [(size_t)BS * CQK_W];   // [:,0:1024]=cq, [:,1024:1600]=ckv
__device__ __half g_q   [(size_t)BS * QW];
__device__ __half g_kv  [(size_t)BS * KVW];
__device__ __half g_attn[(size_t)BS * HID];
// transposed fp16 weights
#define WDN_SZ  (1600*2048)   // merged Wq_down|Wkv_down, [1600,2048]
#define WQU_SZ  (3072*1024)
#define WKU_SZ  (4096*512)
#define WO_SZ   (2048*2048)
#define O_WDN 0
#define O_WQU (O_WDN + WDN_SZ)
#define O_WKU (O_WQU + WQU_SZ)
#define O_WO  (O_WKU + WKU_SZ)
#define W_TOTAL (O_WO + WO_SZ)
__device__ __half g_w[W_TOTAL];

// ---------------- helpers ----------------
__device__ __forceinline__ uint32_t smem_u32(const void* p) {
    uint32_t a;
    asm("{ .reg .u64 t; cvta.to.shared.u64 t, %1; cvt.u32.u64 %0, t; }"
        : "=r"(a) : "l"(p));
    return a;
}
__device__ __forceinline__ void ldm_x4(uint32_t addr, uint32_t r[4]) {
    asm volatile("ldmatrix.sync.aligned.m8n8.x4.shared.b16 {%0,%1,%2,%3}, [%4];"
                 : "=r"(r[0]), "=r"(r[1]), "=r"(r[2]), "=r"(r[3]) : "r"(addr));
}
__device__ __forceinline__ void ldm_x4_t(uint32_t addr, uint32_t r[4]) {
    asm volatile("ldmatrix.sync.aligned.m8n8.x4.trans.shared.b16 {%0,%1,%2,%3}, [%4];"
                 : "=r"(r[0]), "=r"(r[1]), "=r"(r[2]), "=r"(r[3]) : "r"(addr));
}
__device__ __forceinline__ void mma_f16(float d[4], const uint32_t a[4],
                                        const uint32_t b0, const uint32_t b1) {
    asm volatile("mma.sync.aligned.m16n8k16.row.col.f32.f16.f16.f32 "
                 "{%0,%1,%2,%3}, {%4,%5,%6,%7}, {%8,%9}, {%0,%1,%2,%3};"
                 : "+f"(d[0]), "+f"(d[1]), "+f"(d[2]), "+f"(d[3])
                 : "r"(a[0]), "r"(a[1]), "r"(a[2]), "r"(a[3]), "r"(b0), "r"(b1));
}
__device__ __forceinline__ uint32_t packh2(float lo, float hi) {
    uint32_t d;
    asm("cvt.rn.f16x2.f32 %0, %1, %2;" : "=r"(d) : "f"(hi), "f"(lo));
    return d;
}
__device__ __forceinline__ float ex2(float x) {
    float y;
    asm("ex2.approx.f32 %0, %1;" : "=f"(y) : "f"(x));
    return y;
}
#define CPA(s, g) asm volatile("cp.async.cg.shared.global [%0], [%1], 16;" :: "r"(s), "l"(g))
#define CPA_COMMIT() asm volatile("cp.async.commit_group;")
#define CPA_WAIT(n)  asm volatile("cp.async.wait_group %0;" :: "n"(n))

__device__ __forceinline__ uint32_t sw128(uint32_t base, int row, int db) {
    return base + row * 128 + (uint32_t)(db ^ ((row & 7) << 4));
}

// =====================================================================
// prep: fused x->fp16 conversion + all 5 weight transposes (one launch)
// =====================================================================
#define CVT_BLKS   16384
#define WDNQ_BLKS  2048
#define WDNK_BLKS  1152
#define WQU_BLKS   3072
#define WKU_BLKS   2048
#define WO_BLKS    4096
#define PREP_BLKS  (CVT_BLKS + WDNQ_BLKS + WDNK_BLKS + WQU_BLKS + WKU_BLKS + WO_BLKS)

__global__ __launch_bounds__(256)
void prep(const float* __restrict__ x,
          const float* __restrict__ Wq_down, const float* __restrict__ Wkv_down,
          const float* __restrict__ Wq_up,   const float* __restrict__ Wkv_up,
          const float* __restrict__ Wout,
          __half* __restrict__ x16, __half* __restrict__ w)
{
    __shared__ float t[32][33];
    const int bid = blockIdx.x;
    if (bid < CVT_BLKS) {
        int i = bid * 256 + threadIdx.x;
        float2 v = ((const float2*)x)[i];
        ((__half2*)x16)[i] = __float22half2_rn(v);
        return;
    }
    int tb = bid - CVT_BLKS;
    const float* W;
    __half* dst;
    int K, N, nt;
    if (tb < WDNQ_BLKS) {
        W = Wq_down; dst = w + O_WDN; K = 2048; N = 1024; nt = 32;
    } else if ((tb -= WDNQ_BLKS) < WDNK_BLKS) {
        W = Wkv_down; dst = w + O_WDN + (size_t)1024 * 2048; K = 2048; N = 576; nt = 18;
    } else if ((tb -= WDNK_BLKS) < WQU_BLKS) {
        W = Wq_up; dst = w + O_WQU; K = 1024; N = 3072; nt = 96;
    } else if ((tb -= WQU_BLKS) < WKU_BLKS) {
        W = Wkv_up; dst = w + O_WKU; K = 512; N = 4096; nt = 128;
    } else {
        tb -= WKU_BLKS;
        W = Wout; dst = w + O_WO; K = 2048; N = 2048; nt = 64;
    }
    const int n0 = (tb % nt) * 32, k0 = (tb / nt) * 32;
    const int tx = threadIdx.x & 31, ty = threadIdx.x >> 5;
    #pragma unroll
    for (int j = 0; j < 4; j++)
        t[ty + 8*j][tx] = W[(size_t)(k0 + ty + 8*j) * N + n0 + tx];
    __syncthreads();
    #pragma unroll
    for (int j = 0; j < 4; j++)
        dst[(size_t)(n0 + ty + 8*j) * K + k0 + tx] = __float2half_rn(t[tx][ty + 8*j]);
}

// =====================================================================
// fp16 single-pass GEMM body (R12 single-sync pipeline)
// =====================================================================
#define GBUF 32768
#define GEMM_SMEM (3*GBUF)

__device__ __forceinline__
void gemm_body(const __half* __restrict__ A, const __half* __restrict__ B,
               __half* __restrict__ C16, float* __restrict__ C32,
               int M, int N, int K, int lda, int ldc, int bx, int by)
{
    extern __shared__ char sm[];
    const uint32_t sb = smem_u32(sm);
    const int tid  = threadIdx.x;
    const int lane = tid & 31;
    const int wid  = tid >> 5;
    const int wm   = (wid >> 2) * 64;
    const int wn   = (wid & 3) * 32;
    const int m0   = by * 128;
    const int n0   = bx * 128;

    float acc[4][4][4];
    #pragma unroll
    for (int i = 0; i < 4; i++)
        #pragma unroll
        for (int j = 0; j < 4; j++)
            #pragma unroll
            for (int c = 0; c < 4; c++) acc[i][j][c] = 0.f;

    const int T = K >> 6;
    const int arow = tid >> 1, ac = (tid & 1) * 4;

    auto issue = [&](int t) {
        const uint32_t bb = sb + (t % 3) * GBUF;
        const int k0 = t << 6;
        const char* ga = (const char*)(A + (size_t)(m0 + arow) * lda + k0) + ac * 16;
        #pragma unroll
        for (int c = 0; c < 4; c++)
            CPA(sw128(bb, arow, (ac + c) * 16), ga + c * 16);
        int n = n0 + arow;
        if (n >= N) n = N - 1;
        const char* gb = (const char*)(B + (size_t)n * K + k0) + ac * 16;
        #pragma unroll
        for (int c = 0; c < 4; c++)
            CPA(sw128(bb + 16384, arow, (ac + c) * 16), gb + c * 16);
        CPA_COMMIT();
    };

    issue(0);
    if (T > 1) issue(1);

    for (int t = 0; t < T; t++) {
        if (t + 1 < T) CPA_WAIT(1); else CPA_WAIT(0);
        __syncthreads();

        const uint32_t bb = sb + (t % 3) * GBUF;
        const int klo = (lane >> 4) << 4;

        #pragma unroll
        for (int ks = 0; ks < 4; ks++) {
            uint32_t af[4][4];
            #pragma unroll
            for (int mi = 0; mi < 4; mi++)
                ldm_x4(sw128(bb, wm + mi * 16 + (lane & 15), ks * 32 + klo), af[mi]);
            uint32_t bf[4][2];
            #pragma unroll
            for (int np = 0; np < 2; np++) {
                uint32_t q[4];
                ldm_x4(sw128(bb + 16384, wn + np * 16 + (lane & 15), ks * 32 + klo), q);
                bf[2*np][0] = q[0]; bf[2*np][1] = q[2];
                bf[2*np+1][0] = q[1]; bf[2*np+1][1] = q[3];
            }
            #pragma unroll
            for (int mi = 0; mi < 4; mi++)
                #pragma unroll
                for (int ni = 0; ni < 4; ni++)
                    mma_f16(acc[mi][ni], af[mi], bf[ni][0], bf[ni][1]);
            if (ks == 0 && t + 2 < T)
                issue(t + 2);
        }
    }

    const int r0 = lane >> 2, c0 = (lane & 3) * 2;
    #pragma unroll
    for (int mi = 0; mi < 4; mi++) {
        #pragma unroll
        for (int ni = 0; ni < 4; ni++) {
            int row = m0 + wm + mi * 16 + r0;
            int col = n0 + wn + ni * 8 + c0;
            if (col < N) {
                if (C32) {
                    *(float2*)(C32 + (size_t)row * ldc + col) =
                        make_float2(acc[mi][ni][0], acc[mi][ni][1]);
                    *(float2*)(C32 + (size_t)(row + 8) * ldc + col) =
                        make_float2(acc[mi][ni][2], acc[mi][ni][3]);
                } else {
                    *(uint32_t*)(C16 + (size_t)row * ldc + col) =
                        packh2(acc[mi][ni][0], acc[mi][ni][1]);
                    *(uint32_t*)(C16 + (size_t)(row + 8) * ldc + col) =
                        packh2(acc[mi][ni][2], acc[mi][ni][3]);
                }
            }
        }
    }
}

__global__ __launch_bounds__(256, 2)
void gemm_f16(const __half* __restrict__ A, const __half* __restrict__ B,
              __half* __restrict__ C16, float* __restrict__ C32,
              int M, int N, int K, int lda, int ldc)
{
    gemm_body(A, B, C16, C32, M, N, K, lda, ldc, blockIdx.x, blockIdx.y);
}

// fused q-up (24 x-tiles) + kv-up (32 x-tiles); grid (56, 32)
__global__ __launch_bounds__(256, 2)
void gemm_up(const __half* __restrict__ cqk,
             const __half* __restrict__ wqu, const __half* __restrict__ wku,
             __half* __restrict__ qb, __half* __restrict__ kvb)
{
    if (blockIdx.x < QW / 128)
        gemm_body(cqk, wqu, qb, nullptr, BS, QW, QLORA, CQK_W, QW,
                  blockIdx.x, blockIdx.y);
    else
        gemm_body(cqk + 1024, wku, kvb, nullptr, BS, KVW, KVL, CQK_W, KVW,
                  blockIdx.x - QW / 128, blockIdx.y);
}

// =====================================================================
// RoPE on fp16 q and ckv
// =====================================================================
__global__ void rope_kernel(__half* __restrict__ q, __half* __restrict__ cqk,
                            const int* __restrict__ position)
{
    int idx = blockIdx.x * blockDim.x + threadIdx.x;
    const int total = BS * 17 * 32;
    if (idx >= total) return;
    int j = idx & 31;
    int rest = idx >> 5;
    int h = rest % 17;
    int bs = rest / 17;
    int s = bs & (SEQ - 1);

    float pos = (float)position[s];
    float inv = __expf(-(float)(2 * j) * (9.210340371976184f / 64.0f));
    float ang = pos * inv;
    float sn, cs;
    sincosf(ang, &sn, &cs);

    __half* base = (h < 16)
        ? (q + (size_t)bs * QW + h * QH + NOPE)
        : (cqk + (size_t)bs * CQK_W + 1024 + KVL);
    float t1 = __half2float(base[j]);
    float t2 = __half2float(base[j + 32]);
    base[j]      = __float2half_rn(t1 * cs - t2 * sn);
    base[j + 32] = __float2half_rn(t2 * cs + t1 * sn);
}

// =====================================================================
// Flash attention fp16 mma — deferred-PV software pipeline:
// iter t: S(t); issue(t+1); [rescale+PV(t-1)] || [softmax(t)] interleaved.
// K double-buffered, V TRIPLE-buffered (V(t-1) stays live one extra iter).
// smem: 2*24K + 3*16K = 96KB; 2 CTAs/SM.
// Per-thread l partials (sum shuffles hoisted out of the loop).
// =====================================================================
#define KBUF 24576
#define VBUF 16384
#define ATTN_SMEM (2*KBUF + 3*VBUF)   // 98304

__device__ __forceinline__ uint32_t kaddr(uint32_t base, int row, int db) {
    uint32_t within = (uint32_t)(db & 127) ^ (uint32_t)((row & 7) << 4);
    return base + row * 384 + (uint32_t)(db & ~127) + within;
}
__device__ __forceinline__ uint32_t vaddr(uint32_t base, int row, int db) {
    uint32_t within = (uint32_t)(db & 127) ^ (uint32_t)((row & 7) << 4);
    return base + row * 256 + (uint32_t)(db & ~127) + within;
}

__global__ __launch_bounds__(128)
void attn_mma(const __half* __restrict__ q16, const __half* __restrict__ kv16,
              const __half* __restrict__ cqk, __half* __restrict__ out)
{
    extern __shared__ char sm[];
    const uint32_t sb = smem_u32(sm);
    const int b = blockIdx.z, h = blockIdx.y, q0 = blockIdx.x * 64;
    const int tid = threadIdx.x, lane = tid & 31, w = tid >> 5;

    // ---- prologue: Q tile -> kbuf0, extract fragments ----
    #pragma unroll
    for (int i = 0; i < 12; i++) {
        int idx = tid + i * 128;
        int row = idx / 24, c16 = idx % 24;
        const char* g = (const char*)(q16 +
            (size_t)(b * SEQ + q0 + row) * QW + h * QH) + c16 * 16;
        CPA(kaddr(sb, row, c16 * 16), g);
    }
    CPA_COMMIT();
    CPA_WAIT(0);
    __syncthreads();

    uint32_t qa[12][4];
    {
        int r = w * 16 + (lane & 15);
        int dhi = (lane >> 4) * 16;
        #pragma unroll
        for (int ks = 0; ks < 12; ks++)
            ldm_x4(kaddr(sb, r, ks * 32 + dhi), qa[ks]);
    }
    __syncthreads();

    // ---- K/V tile issuer: K -> kbuf[kt&1], V -> vbuf[kt%3] ----
    auto issue = [&](int kt) {
        const uint32_t kb = sb + (kt & 1) * KBUF;
        const uint32_t vb = sb + 2 * KBUF + (kt % 3) * VBUF;
        const int key0 = kt * 64;
        #pragma unroll
        for (int i = 0; i < 12; i++) {
            int idx = tid + i * 128;
            int row = idx / 24, c16 = idx % 24;
            size_t trow = (size_t)(b * SEQ + key0 + row);
            const char* g = (c16 < 16)
                ? (const char*)(kv16 + trow * KVW + h * 256) + c16 * 16
                : (const char*)(cqk + trow * CQK_W + 1536) + (c16 - 16) * 16;
            CPA(kaddr(kb, row, c16 * 16), g);
        }
        #pragma unroll
        for (int i = 0; i < 8; i++) {
            int idx = tid + i * 128;
            int row = idx >> 4, c16 = idx & 15;
            const char* g = (const char*)(kv16 +
                (size_t)(b * SEQ + key0 + row) * KVW + h * 256 + 128) + c16 * 16;
            CPA(vaddr(vb, row, c16 * 16), g);
        }
        CPA_COMMIT();
    };

    float o[16][4];
    #pragma unroll
    for (int i = 0; i < 16; i++)
        #pragma unroll
        for (int j = 0; j < 4; j++) o[i][j] = 0.f;
    float m0 = -1e30f, m1 = -1e30f, l0 = 0.f, l1 = 0.f;
    uint32_t pa_prev[4][4];
    float ap0 = 0.f, ap1 = 0.f;
    const float sc2 = 0.07216878364870323f * 1.4426950408889634f;
    const int vrow_off = ((lane >> 3) & 1) * 8 + (lane & 7);
    const int vdim_off = (lane >> 4) * 16;

    // deferred PV step: rescale o, then O += P_prev * V(kt_prev)
    auto pv_step = [&](int kt_prev) {
        const uint32_t vb = sb + 2 * KBUF + (kt_prev % 3) * VBUF;
        #pragma unroll
        for (int nj = 0; nj < 16; nj++) {
            o[nj][0] *= ap0; o[nj][1] *= ap0;
            o[nj][2] *= ap1; o[nj][3] *= ap1;
        }
        #pragma unroll
        for (int kk = 0; kk < 4; kk++) {
            #pragma unroll
            for (int nb = 0; nb < 8; nb++) {
                uint32_t r[4];
                ldm_x4_t(vaddr(vb, kk * 16 + vrow_off, nb * 32 + vdim_off), r);
                mma_f16(o[2 * nb],     pa_prev[kk], r[0], r[1]);
                mma_f16(o[2 * nb + 1], pa_prev[kk], r[2], r[3]);
            }
        }
    };

    issue(0);
    const int T = SEQ / 64;

    for (int kt = 0; kt < T; kt++) {
        CPA_WAIT(0);
        __syncthreads();   // tile kt resident; all warps done with old buffers

        const uint32_t kb = sb + (kt & 1) * KBUF;

        // ---- S = Q K^T(kt) ----
        float s[8][4];
        #pragma unroll
        for (int i = 0; i < 8; i++)
            #pragma unroll
            for (int j = 0; j < 4; j++) s[i][j] = 0.f;

        const int krow_off = ((lane >> 4) << 3) + (lane & 7);
        const int kdim_off = ((lane >> 3) & 1) * 16;
        #pragma unroll
        for (int ks = 0; ks < 12; ks++) {
            #pragma unroll
            for (int kb4 = 0; kb4 < 4; kb4++) {
                uint32_t r[4];
                ldm_x4(kaddr(kb, kb4 * 16 + krow_off, ks * 32 + kdim_off), r);
                mma_f16(s[2 * kb4],     qa[ks], r[0], r[1]);
                mma_f16(s[2 * kb4 + 1], qa[ks], r[2], r[3]);
            }
        }

        if (kt + 1 < T) issue(kt + 1);   // post-sync: buffers (kt+1)&1 / (kt+1)%3 are free

        // ---- deferred PV(kt-1): independent of softmax(kt); interleaves ----
        if (kt > 0) pv_step(kt - 1);

        // ---- softmax(kt), exp2 domain ----
        float mx0 = -1e30f, mx1 = -1e30f;
        #pragma unroll
        for (int ni = 0; ni < 8; ni++) {
            mx0 = fmaxf(mx0, fmaxf(s[ni][0], s[ni][1]));
            mx1 = fmaxf(mx1, fmaxf(s[ni][2], s[ni][3]));
        }
        mx0 = fmaxf(mx0, __shfl_xor_sync(0xffffffffu, mx0, 1));
        mx0 = fmaxf(mx0, __shfl_xor_sync(0xffffffffu, mx0, 2));
        mx1 = fmaxf(mx1, __shfl_xor_sync(0xffffffffu, mx1, 1));
        mx1 = fmaxf(mx1, __shfl_xor_sync(0xffffffffu, mx1, 2));

        float mn0 = fmaxf(m0, mx0 * sc2);
        float mn1 = fmaxf(m1, mx1 * sc2);
        float a0 = ex2(m0 - mn0);
        float a1 = ex2(m1 - mn1);

        float rs0 = 0.f, rs1 = 0.f;
        #pragma unroll
        for (int ni = 0; ni < 8; ni++) {
            float p0 = ex2(fmaf(s[ni][0], sc2, -mn0));
            float p1 = ex2(fmaf(s[ni][1], sc2, -mn0));
            float p2 = ex2(fmaf(s[ni][2], sc2, -mn1));
            float p3 = ex2(fmaf(s[ni][3], sc2, -mn1));
            rs0 += p0 + p1;
            rs1 += p2 + p3;
            int kk = ni >> 1;
            if ((ni & 1) == 0) {
                pa_prev[kk][0] = packh2(p0, p1);
                pa_prev[kk][1] = packh2(p2, p3);
            } else {
                pa_prev[kk][2] = packh2(p0, p1);
                pa_prev[kk][3] = packh2(p2, p3);
            }
        }
        // per-thread partial l (row-uniform a makes this exact up to fp assoc.)
        l0 = l0 * a0 + rs0;
        l1 = l1 * a1 + rs1;
        m0 = mn0; m1 = mn1;
        ap0 = a0; ap1 = a1;
    }

    // ---- drain: final PV(T-1) ----
    pv_step(T - 1);

    // ---- l reduction (hoisted out of the loop) + normalize + store ----
    l0 += __shfl_xor_sync(0xffffffffu, l0, 1);
    l0 += __shfl_xor_sync(0xffffffffu, l0, 2);
    l1 += __shfl_xor_sync(0xffffffffu, l1, 1);
    l1 += __shfl_xor_sync(0xffffffffu, l1, 2);

    const float inv0 = 1.f / l0, inv1 = 1.f / l1;
    size_t rbase = (size_t)(b * SEQ + q0 + w * 16 + (lane >> 2)) * HID
                 + h * VH + (lane & 3) * 2;
    #pragma unroll
    for (int nj = 0; nj < 16; nj++) {
        *(uint32_t*)(out + rbase + nj * 8) =
            packh2(o[nj][0] * inv0, o[nj][1] * inv0);
        *(uint32_t*)(out + rbase + 8 * HID + nj * 8) =
            packh2(o[nj][2] * inv1, o[nj][3] * inv1);
    }
}

// =====================================================================
extern "C" void kernel_launch(void* const* d_in, const int* in_sizes, int n_in,
                              void* d_out, int out_size)
{
    const float* x        = (const float*)d_in[0];
    const int*   position = (const int*)  d_in[1];
    const float* Wq_down  = (const float*)d_in[2];
    const float* Wq_up    = (const float*)d_in[3];
    const float* Wkv_down = (const float*)d_in[4];
    const float* Wkv_up   = (const float*)d_in[5];
    const float* Wout     = (const float*)d_in[6];
    float*       out      = (float*)d_out;

    __half *x16, *cqk, *qb, *kvb, *attn, *w;
    cudaGetSymbolAddress((void**)&x16,  g_x16);
    cudaGetSymbolAddress((void**)&cqk,  g_cqk);
    cudaGetSymbolAddress((void**)&qb,   g_q);
    cudaGetSymbolAddress((void**)&kvb,  g_kv);
    cudaGetSymbolAddress((void**)&attn, g_attn);
    cudaGetSymbolAddress((void**)&w,    g_w);

    cudaFuncSetAttribute(gemm_f16, cudaFuncAttributeMaxDynamicSharedMemorySize,
                         GEMM_SMEM);
    cudaFuncSetAttribute(gemm_up, cudaFuncAttributeMaxDynamicSharedMemorySize,
                         GEMM_SMEM);
    cudaFuncSetAttribute(attn_mma, cudaFuncAttributeMaxDynamicSharedMemorySize,
                         ATTN_SMEM);

    // 1. fused conversions (x + all weights)
    prep<<<PREP_BLKS, 256>>>(x, Wq_down, Wkv_down, Wq_up, Wkv_up, Wout, x16, w);

    // 2. merged down-projection: cqk = x16 @ [Wq_down|Wkv_down]
    gemm_f16<<<dim3((CQK_W + 127)/128, BS/128), 256, GEMM_SMEM>>>(
        x16, w + O_WDN, cqk, nullptr, BS, CQK_W, HID, HID, CQK_W);

    // 3. fused up-projections: q = cq @ Wq_up  ||  kv = ckv @ Wkv_up
    gemm_up<<<dim3(QW/128 + KVW/128, BS/128), 256, GEMM_SMEM>>>(
        cqk, w + O_WQU, w + O_WKU, qb, kvb);

    // 4. RoPE (q rope dims + k rope in cqk)
    rope_kernel<<<(BS*17*32 + 255)/256, 256>>>(qb, cqk, position);

    // 5. attention (deferred-PV pipeline)
    attn_mma<<<dim3(SEQ/64, HEADS, BATCH), 128, ATTN_SMEM>>>(qb, kvb, cqk, attn);

    // 6. output projection
    gemm_f16<<<dim3(HID/128, BS/128), 256, GEMM_SMEM>>>(
        attn, w + O_WO, nullptr, out, BS, HID, HID, HID, HID);
}

// round 14
// speedup vs baseline: 1.0403x; 1.0403x over previous
#include <cuda_runtime.h>
#include <cuda_fp16.h>
#include <math.h>
#include <stdint.h>

// ---------------- problem dims ----------------
#define HID     2048
#define HEADS   16
#define SEQ     2048
#define BATCH   2
#define BS      (BATCH*SEQ)          // 4096
#define QLORA   1024
#define QH      192
#define NOPE    128
#define ROPED   64
#define VH      128
#define KVL     512
#define CKV_W   576
#define CQK_W   1600                 // QLORA + CKV_W (merged down-proj output)
#define QW      (HEADS*QH)           // 3072
#define KVW     (HEADS*(NOPE+VH))    // 4096

// ---------------- scratch (all fp16 intermediates) ----------------
__device__ __half g_x16 [(size_t)BS * HID];
__device__ __half g_cqk [(size_t)BS * CQK_W];   // [:,0:1024]=cq, [:,1024:1600]=ckv
__device__ __half g_q   [(size_t)BS * QW];
__device__ __half g_kv  [(size_t)BS * KVW];
__device__ __half g_attn[(size_t)BS * HID];
// transposed fp16 weights
#define WDN_SZ  (1600*2048)   // merged Wq_down|Wkv_down, [1600,2048]
#define WQU_SZ  (3072*1024)
#define WKU_SZ  (4096*512)
#define WO_SZ   (2048*2048)
#define O_WDN 0
#define O_WQU (O_WDN + WDN_SZ)
#define O_WKU (O_WQU + WQU_SZ)
#define O_WO  (O_WKU + WKU_SZ)
#define W_TOTAL (O_WO + WO_SZ)
__device__ __half g_w[W_TOTAL];

// ---------------- helpers ----------------
__device__ __forceinline__ uint32_t smem_u32(const void* p) {
    uint32_t a;
    asm("{ .reg .u64 t; cvta.to.shared.u64 t, %1; cvt.u32.u64 %0, t; }"
        : "=r"(a) : "l"(p));
    return a;
}
__device__ __forceinline__ void ldm_x4(uint32_t addr, uint32_t r[4]) {
    asm volatile("ldmatrix.sync.aligned.m8n8.x4.shared.b16 {%0,%1,%2,%3}, [%4];"
                 : "=r"(r[0]), "=r"(r[1]), "=r"(r[2]), "=r"(r[3]) : "r"(addr));
}
__device__ __forceinline__ void ldm_x4_t(uint32_t addr, uint32_t r[4]) {
    asm volatile("ldmatrix.sync.aligned.m8n8.x4.trans.shared.b16 {%0,%1,%2,%3}, [%4];"
                 : "=r"(r[0]), "=r"(r[1]), "=r"(r[2]), "=r"(r[3]) : "r"(addr));
}
__device__ __forceinline__ void mma_f16(float d[4], const uint32_t a[4],
                                        const uint32_t b0, const uint32_t b1) {
    asm volatile("mma.sync.aligned.m16n8k16.row.col.f32.f16.f16.f32 "
                 "{%0,%1,%2,%3}, {%4,%5,%6,%7}, {%8,%9}, {%0,%1,%2,%3};"
                 : "+f"(d[0]), "+f"(d[1]), "+f"(d[2]), "+f"(d[3])
                 : "r"(a[0]), "r"(a[1]), "r"(a[2]), "r"(a[3]), "r"(b0), "r"(b1));
}
__device__ __forceinline__ uint32_t packh2(float lo, float hi) {
    uint32_t d;
    asm("cvt.rn.f16x2.f32 %0, %1, %2;" : "=r"(d) : "f"(hi), "f"(lo));
    return d;
}
__device__ __forceinline__ float ex2(float x) {
    float y;
    asm("ex2.approx.f32 %0, %1;" : "=f"(y) : "f"(x));
    return y;
}
#define CPA(s, g) asm volatile("cp.async.cg.shared.global [%0], [%1], 16;" :: "r"(s), "l"(g))
#define CPA_COMMIT() asm volatile("cp.async.commit_group;")
#define CPA_WAIT(n)  asm volatile("cp.async.wait_group %0;" :: "n"(n))

__device__ __forceinline__ uint32_t sw128(uint32_t base, int row, int db) {
    return base + row * 128 + (uint32_t)(db ^ ((row & 7) << 4));
}

// =====================================================================
// prep: fused x->fp16 conversion + all 5 weight transposes (one launch)
// =====================================================================
#define CVT_BLKS   16384
#define WDNQ_BLKS  2048
#define WDNK_BLKS  1152
#define WQU_BLKS   3072
#define WKU_BLKS   2048
#define WO_BLKS    4096
#define PREP_BLKS  (CVT_BLKS + WDNQ_BLKS + WDNK_BLKS + WQU_BLKS + WKU_BLKS + WO_BLKS)

__global__ __launch_bounds__(256)
void prep(const float* __restrict__ x,
          const float* __restrict__ Wq_down, const float* __restrict__ Wkv_down,
          const float* __restrict__ Wq_up,   const float* __restrict__ Wkv_up,
          const float* __restrict__ Wout,
          __half* __restrict__ x16, __half* __restrict__ w)
{
    __shared__ float t[32][33];
    const int bid = blockIdx.x;
    if (bid < CVT_BLKS) {
        int i = bid * 256 + threadIdx.x;
        float2 v = ((const float2*)x)[i];
        ((__half2*)x16)[i] = __float22half2_rn(v);
        return;
    }
    int tb = bid - CVT_BLKS;
    const float* W;
    __half* dst;
    int K, N, nt;
    if (tb < WDNQ_BLKS) {
        W = Wq_down; dst = w + O_WDN; K = 2048; N = 1024; nt = 32;
    } else if ((tb -= WDNQ_BLKS) < WDNK_BLKS) {
        W = Wkv_down; dst = w + O_WDN + (size_t)1024 * 2048; K = 2048; N = 576; nt = 18;
    } else if ((tb -= WDNK_BLKS) < WQU_BLKS) {
        W = Wq_up; dst = w + O_WQU; K = 1024; N = 3072; nt = 96;
    } else if ((tb -= WQU_BLKS) < WKU_BLKS) {
        W = Wkv_up; dst = w + O_WKU; K = 512; N = 4096; nt = 128;
    } else {
        tb -= WKU_BLKS;
        W = Wout; dst = w + O_WO; K = 2048; N = 2048; nt = 64;
    }
    const int n0 = (tb % nt) * 32, k0 = (tb / nt) * 32;
    const int tx = threadIdx.x & 31, ty = threadIdx.x >> 5;
    #pragma unroll
    for (int j = 0; j < 4; j++)
        t[ty + 8*j][tx] = W[(size_t)(k0 + ty + 8*j) * N + n0 + tx];
    __syncthreads();
    #pragma unroll
    for (int j = 0; j < 4; j++)
        dst[(size_t)(n0 + ty + 8*j) * K + k0 + tx] = __float2half_rn(t[tx][ty + 8*j]);
}

// =====================================================================
// fp16 single-pass GEMM body (R12 single-sync pipeline)
// =====================================================================
#define GBUF 32768
#define GEMM_SMEM (3*GBUF)

__device__ __forceinline__
void gemm_body(const __half* __restrict__ A, const __half* __restrict__ B,
               __half* __restrict__ C16, float* __restrict__ C32,
               int M, int N, int K, int lda, int ldc, int bx, int by)
{
    extern __shared__ char sm[];
    const uint32_t sb = smem_u32(sm);
    const int tid  = threadIdx.x;
    const int lane = tid & 31;
    const int wid  = tid >> 5;
    const int wm   = (wid >> 2) * 64;
    const int wn   = (wid & 3) * 32;
    const int m0   = by * 128;
    const int n0   = bx * 128;

    float acc[4][4][4];
    #pragma unroll
    for (int i = 0; i < 4; i++)
        #pragma unroll
        for (int j = 0; j < 4; j++)
            #pragma unroll
            for (int c = 0; c < 4; c++) acc[i][j][c] = 0.f;

    const int T = K >> 6;
    const int arow = tid >> 1, ac = (tid & 1) * 4;

    auto issue = [&](int t) {
        const uint32_t bb = sb + (t % 3) * GBUF;
        const int k0 = t << 6;
        const char* ga = (const char*)(A + (size_t)(m0 + arow) * lda + k0) + ac * 16;
        #pragma unroll
        for (int c = 0; c < 4; c++)
            CPA(sw128(bb, arow, (ac + c) * 16), ga + c * 16);
        int n = n0 + arow;
        if (n >= N) n = N - 1;
        const char* gb = (const char*)(B + (size_t)n * K + k0) + ac * 16;
        #pragma unroll
        for (int c = 0; c < 4; c++)
            CPA(sw128(bb + 16384, arow, (ac + c) * 16), gb + c * 16);
        CPA_COMMIT();
    };

    issue(0);
    if (T > 1) issue(1);

    for (int t = 0; t < T; t++) {
        if (t + 1 < T) CPA_WAIT(1); else CPA_WAIT(0);
        __syncthreads();

        const uint32_t bb = sb + (t % 3) * GBUF;
        const int klo = (lane >> 4) << 4;

        #pragma unroll
        for (int ks = 0; ks < 4; ks++) {
            uint32_t af[4][4];
            #pragma unroll
            for (int mi = 0; mi < 4; mi++)
                ldm_x4(sw128(bb, wm + mi * 16 + (lane & 15), ks * 32 + klo), af[mi]);
            uint32_t bf[4][2];
            #pragma unroll
            for (int np = 0; np < 2; np++) {
                uint32_t q[4];
                ldm_x4(sw128(bb + 16384, wn + np * 16 + (lane & 15), ks * 32 + klo), q);
                bf[2*np][0] = q[0]; bf[2*np][1] = q[2];
                bf[2*np+1][0] = q[1]; bf[2*np+1][1] = q[3];
            }
            #pragma unroll
            for (int mi = 0; mi < 4; mi++)
                #pragma unroll
                for (int ni = 0; ni < 4; ni++)
                    mma_f16(acc[mi][ni], af[mi], bf[ni][0], bf[ni][1]);
            if (ks == 0 && t + 2 < T)
                issue(t + 2);
        }
    }

    const int r0 = lane >> 2, c0 = (lane & 3) * 2;
    #pragma unroll
    for (int mi = 0; mi < 4; mi++) {
        #pragma unroll
        for (int ni = 0; ni < 4; ni++) {
            int row = m0 + wm + mi * 16 + r0;
            int col = n0 + wn + ni * 8 + c0;
            if (col < N) {
                if (C32) {
                    *(float2*)(C32 + (size_t)row * ldc + col) =
                        make_float2(acc[mi][ni][0], acc[mi][ni][1]);
                    *(float2*)(C32 + (size_t)(row + 8) * ldc + col) =
                        make_float2(acc[mi][ni][2], acc[mi][ni][3]);
                } else {
                    *(uint32_t*)(C16 + (size_t)row * ldc + col) =
                        packh2(acc[mi][ni][0], acc[mi][ni][1]);
                    *(uint32_t*)(C16 + (size_t)(row + 8) * ldc + col) =
                        packh2(acc[mi][ni][2], acc[mi][ni][3]);
                }
            }
        }
    }
}

__global__ __launch_bounds__(256, 2)
void gemm_f16(const __half* __restrict__ A, const __half* __restrict__ B,
              __half* __restrict__ C16, float* __restrict__ C32,
              int M, int N, int K, int lda, int ldc)
{
    gemm_body(A, B, C16, C32, M, N, K, lda, ldc, blockIdx.x, blockIdx.y);
}

// fused q-up (24 x-tiles) + kv-up (32 x-tiles); grid (56, 32)
__global__ __launch_bounds__(256, 2)
void gemm_up(const __half* __restrict__ cqk,
             const __half* __restrict__ wqu, const __half* __restrict__ wku,
             __half* __restrict__ qb, __half* __restrict__ kvb)
{
    if (blockIdx.x < QW / 128)
        gemm_body(cqk, wqu, qb, nullptr, BS, QW, QLORA, CQK_W, QW,
                  blockIdx.x, blockIdx.y);
    else
        gemm_body(cqk + 1024, wku, kvb, nullptr, BS, KVW, KVL, CQK_W, KVW,
                  blockIdx.x - QW / 128, blockIdx.y);
}

// =====================================================================
// RoPE on fp16 q and ckv
// =====================================================================
__global__ void rope_kernel(__half* __restrict__ q, __half* __restrict__ cqk,
                            const int* __restrict__ position)
{
    int idx = blockIdx.x * blockDim.x + threadIdx.x;
    const int total = BS * 17 * 32;
    if (idx >= total) return;
    int j = idx & 31;
    int rest = idx >> 5;
    int h = rest % 17;
    int bs = rest / 17;
    int s = bs & (SEQ - 1);

    float pos = (float)position[s];
    float inv = __expf(-(float)(2 * j) * (9.210340371976184f / 64.0f));
    float ang = pos * inv;
    float sn, cs;
    sincosf(ang, &sn, &cs);

    __half* base = (h < 16)
        ? (q + (size_t)bs * QW + h * QH + NOPE)
        : (cqk + (size_t)bs * CQK_W + 1024 + KVL);
    float t1 = __half2float(base[j]);
    float t2 = __half2float(base[j + 32]);
    base[j]      = __float2half_rn(t1 * cs - t2 * sn);
    base[j + 32] = __float2half_rn(t2 * cs + t1 * sn);
}

// =====================================================================
// Flash attention fp16 mma — deferred-PV with FULL R8 prefetch depth:
//   iter kt: issue(kt+1); WAIT(1); sync; S(kt); PV(kt-1)+softmax(kt); sync
// K double-buffered, V triple-buffered. smem 96KB, 2 CTAs/SM.
// =====================================================================
#define KBUF 24576
#define VBUF 16384
#define ATTN_SMEM (2*KBUF + 3*VBUF)   // 98304

__device__ __forceinline__ uint32_t kaddr(uint32_t base, int row, int db) {
    uint32_t within = (uint32_t)(db & 127) ^ (uint32_t)((row & 7) << 4);
    return base + row * 384 + (uint32_t)(db & ~127) + within;
}
__device__ __forceinline__ uint32_t vaddr(uint32_t base, int row, int db) {
    uint32_t within = (uint32_t)(db & 127) ^ (uint32_t)((row & 7) << 4);
    return base + row * 256 + (uint32_t)(db & ~127) + within;
}

__global__ __launch_bounds__(128)
void attn_mma(const __half* __restrict__ q16, const __half* __restrict__ kv16,
              const __half* __restrict__ cqk, __half* __restrict__ out)
{
    extern __shared__ char sm[];
    const uint32_t sb = smem_u32(sm);
    const int b = blockIdx.z, h = blockIdx.y, q0 = blockIdx.x * 64;
    const int tid = threadIdx.x, lane = tid & 31, w = tid >> 5;

    // ---- prologue: Q tile -> kbuf0, extract fragments ----
    #pragma unroll
    for (int i = 0; i < 12; i++) {
        int idx = tid + i * 128;
        int row = idx / 24, c16 = idx % 24;
        const char* g = (const char*)(q16 +
            (size_t)(b * SEQ + q0 + row) * QW + h * QH) + c16 * 16;
        CPA(kaddr(sb, row, c16 * 16), g);
    }
    CPA_COMMIT();
    CPA_WAIT(0);
    __syncthreads();

    uint32_t qa[12][4];
    {
        int r = w * 16 + (lane & 15);
        int dhi = (lane >> 4) * 16;
        #pragma unroll
        for (int ks = 0; ks < 12; ks++)
            ldm_x4(kaddr(sb, r, ks * 32 + dhi), qa[ks]);
    }
    __syncthreads();

    // ---- K/V tile issuer: K -> kbuf[kt&1], V -> vbuf[kt%3] ----
    auto issue = [&](int kt) {
        const uint32_t kb = sb + (kt & 1) * KBUF;
        const uint32_t vb = sb + 2 * KBUF + (kt % 3) * VBUF;
        const int key0 = kt * 64;
        #pragma unroll
        for (int i = 0; i < 12; i++) {
            int idx = tid + i * 128;
            int row = idx / 24, c16 = idx % 24;
            size_t trow = (size_t)(b * SEQ + key0 + row);
            const char* g = (c16 < 16)
                ? (const char*)(kv16 + trow * KVW + h * 256) + c16 * 16
                : (const char*)(cqk + trow * CQK_W + 1536) + (c16 - 16) * 16;
            CPA(kaddr(kb, row, c16 * 16), g);
        }
        #pragma unroll
        for (int i = 0; i < 8; i++) {
            int idx = tid + i * 128;
            int row = idx >> 4, c16 = idx & 15;
            const char* g = (const char*)(kv16 +
                (size_t)(b * SEQ + key0 + row) * KVW + h * 256 + 128) + c16 * 16;
            CPA(vaddr(vb, row, c16 * 16), g);
        }
        CPA_COMMIT();
    };

    float o[16][4];
    #pragma unroll
    for (int i = 0; i < 16; i++)
        #pragma unroll
        for (int j = 0; j < 4; j++) o[i][j] = 0.f;
    float m0 = -1e30f, m1 = -1e30f, l0 = 0.f, l1 = 0.f;
    uint32_t pa_prev[4][4];
    float ap0 = 0.f, ap1 = 0.f;
    const float sc2 = 0.07216878364870323f * 1.4426950408889634f;
    const int vrow_off = ((lane >> 3) & 1) * 8 + (lane & 7);
    const int vdim_off = (lane >> 4) * 16;

    // deferred PV step: rescale o, then O += P_prev * V(kt_prev)
    auto pv_step = [&](int kt_prev) {
        const uint32_t vb = sb + 2 * KBUF + (kt_prev % 3) * VBUF;
        #pragma unroll
        for (int nj = 0; nj < 16; nj++) {
            o[nj][0] *= ap0; o[nj][1] *= ap0;
            o[nj][2] *= ap1; o[nj][3] *= ap1;
        }
        #pragma unroll
        for (int kk = 0; kk < 4; kk++) {
            #pragma unroll
            for (int nb = 0; nb < 8; nb++) {
                uint32_t r[4];
                ldm_x4_t(vaddr(vb, kk * 16 + vrow_off, nb * 32 + vdim_off), r);
                mma_f16(o[2 * nb],     pa_prev[kk], r[0], r[1]);
                mma_f16(o[2 * nb + 1], pa_prev[kk], r[2], r[3]);
            }
        }
    };

    issue(0);
    const int T = SEQ / 64;

    for (int kt = 0; kt < T; kt++) {
        // full-depth prefetch (R8 style): issue kt+1 BEFORE waiting on kt.
        // K slot (kt+1)&1: S(kt-1) finished before end-sync of kt-1.
        // V slot (kt+1)%3: PV(kt-2) finished before end-sync of kt-1.
        if (kt + 1 < T) {
            issue(kt + 1);
            CPA_WAIT(1);
        } else {
            CPA_WAIT(0);
        }
        __syncthreads();

        const uint32_t kb = sb + (kt & 1) * KBUF;

        // ---- S = Q K^T(kt) ----
        float s[8][4];
        #pragma unroll
        for (int i = 0; i < 8; i++)
            #pragma unroll
            for (int j = 0; j < 4; j++) s[i][j] = 0.f;

        const int krow_off = ((lane >> 4) << 3) + (lane & 7);
        const int kdim_off = ((lane >> 3) & 1) * 16;
        #pragma unroll
        for (int ks = 0; ks < 12; ks++) {
            #pragma unroll
            for (int kb4 = 0; kb4 < 4; kb4++) {
                uint32_t r[4];
                ldm_x4(kaddr(kb, kb4 * 16 + krow_off, ks * 32 + kdim_off), r);
                mma_f16(s[2 * kb4],     qa[ks], r[0], r[1]);
                mma_f16(s[2 * kb4 + 1], qa[ks], r[2], r[3]);
            }
        }

        // ---- deferred PV(kt-1): independent of softmax(kt) → ILP ----
        if (kt > 0) pv_step(kt - 1);

        // ---- softmax(kt), exp2 domain ----
        float mx0 = -1e30f, mx1 = -1e30f;
        #pragma unroll
        for (int ni = 0; ni < 8; ni++) {
            mx0 = fmaxf(mx0, fmaxf(s[ni][0], s[ni][1]));
            mx1 = fmaxf(mx1, fmaxf(s[ni][2], s[ni][3]));
        }
        mx0 = fmaxf(mx0, __shfl_xor_sync(0xffffffffu, mx0, 1));
        mx0 = fmaxf(mx0, __shfl_xor_sync(0xffffffffu, mx0, 2));
        mx1 = fmaxf(mx1, __shfl_xor_sync(0xffffffffu, mx1, 1));
        mx1 = fmaxf(mx1, __shfl_xor_sync(0xffffffffu, mx1, 2));

        float mn0 = fmaxf(m0, mx0 * sc2);
        float mn1 = fmaxf(m1, mx1 * sc2);
        float a0 = ex2(m0 - mn0);
        float a1 = ex2(m1 - mn1);

        float rs0 = 0.f, rs1 = 0.f;
        #pragma unroll
        for (int ni = 0; ni < 8; ni++) {
            float p0 = ex2(fmaf(s[ni][0], sc2, -mn0));
            float p1 = ex2(fmaf(s[ni][1], sc2, -mn0));
            float p2 = ex2(fmaf(s[ni][2], sc2, -mn1));
            float p3 = ex2(fmaf(s[ni][3], sc2, -mn1));
            rs0 += p0 + p1;
            rs1 += p2 + p3;
            int kk = ni >> 1;
            if ((ni & 1) == 0) {
                pa_prev[kk][0] = packh2(p0, p1);
                pa_prev[kk][1] = packh2(p2, p3);
            } else {
                pa_prev[kk][2] = packh2(p0, p1);
                pa_prev[kk][3] = packh2(p2, p3);
            }
        }
        l0 = l0 * a0 + rs0;
        l1 = l1 * a1 + rs1;
        m0 = mn0; m1 = mn1;
        ap0 = a0; ap1 = a1;

        __syncthreads();   // protects K(kt)/V(kt-1) before next iteration's issue
    }

    // ---- drain: final PV(T-1) ----
    pv_step(T - 1);

    // ---- l reduction (hoisted) + normalize + store ----
    l0 += __shfl_xor_sync(0xffffffffu, l0, 1);
    l0 += __shfl_xor_sync(0xffffffffu, l0, 2);
    l1 += __shfl_xor_sync(0xffffffffu, l1, 1);
    l1 += __shfl_xor_sync(0xffffffffu, l1, 2);

    const float inv0 = 1.f / l0, inv1 = 1.f / l1;
    size_t rbase = (size_t)(b * SEQ + q0 + w * 16 + (lane >> 2)) * HID
                 + h * VH + (lane & 3) * 2;
    #pragma unroll
    for (int nj = 0; nj < 16; nj++) {
        *(uint32_t*)(out + rbase + nj * 8) =
            packh2(o[nj][0] * inv0, o[nj][1] * inv0);
        *(uint32_t*)(out + rbase + 8 * HID + nj * 8) =
            packh2(o[nj][2] * inv1, o[nj][3] * inv1);
    }
}

// =====================================================================
extern "C" void kernel_launch(void* const* d_in, const int* in_sizes, int n_in,
                              void* d_out, int out_size)
{
    const float* x        = (const float*)d_in[0];
    const int*   position = (const int*)  d_in[1];
    const float* Wq_down  = (const float*)d_in[2];
    const float* Wq_up    = (const float*)d_in[3];
    const float* Wkv_down = (const float*)d_in[4];
    const float* Wkv_up   = (const float*)d_in[5];
    const float* Wout     = (const float*)d_in[6];
    float*       out      = (float*)d_out;

    __half *x16, *cqk, *qb, *kvb, *attn, *w;
    cudaGetSymbolAddress((void**)&x16,  g_x16);
    cudaGetSymbolAddress((void**)&cqk,  g_cqk);
    cudaGetSymbolAddress((void**)&qb,   g_q);
    cudaGetSymbolAddress((void**)&kvb,  g_kv);
    cudaGetSymbolAddress((void**)&attn, g_attn);
    cudaGetSymbolAddress((void**)&w,    g_w);

    cudaFuncSetAttribute(gemm_f16, cudaFuncAttributeMaxDynamicSharedMemorySize,
                         GEMM_SMEM);
    cudaFuncSetAttribute(gemm_up, cudaFuncAttributeMaxDynamicSharedMemorySize,
                         GEMM_SMEM);
    cudaFuncSetAttribute(attn_mma, cudaFuncAttributeMaxDynamicSharedMemorySize,
                         ATTN_SMEM);

    // 1. fused conversions (x + all weights)
    prep<<<PREP_BLKS, 256>>>(x, Wq_down, Wkv_down, Wq_up, Wkv_up, Wout, x16, w);

    // 2. merged down-projection: cqk = x16 @ [Wq_down|Wkv_down]
    gemm_f16<<<dim3((CQK_W + 127)/128, BS/128), 256, GEMM_SMEM>>>(
        x16, w + O_WDN, cqk, nullptr, BS, CQK_W, HID, HID, CQK_W);

    // 3. fused up-projections: q = cq @ Wq_up  ||  kv = ckv @ Wkv_up
    gemm_up<<<dim3(QW/128 + KVW/128, BS/128), 256, GEMM_SMEM>>>(
        cqk, w + O_WQU, w + O_WKU, qb, kvb);

    // 4. RoPE (q rope dims + k rope in cqk)
    rope_kernel<<<(BS*17*32 + 255)/256, 256>>>(qb, cqk, position);

    // 5. attention (deferred-PV, full prefetch depth)
    attn_mma<<<dim3(SEQ/64, HEADS, BATCH), 128, ATTN_SMEM>>>(qb, kvb, cqk, attn);

    // 6. output projection
    gemm_f16<<<dim3(HID/128, BS/128), 256, GEMM_SMEM>>>(
        attn, w + O_WO, nullptr, out, BS, HID, HID, HID, HID);
}